// round 9
// baseline (speedup 1.0000x reference)
#include <cuda_runtime.h>
#include <cuda_bf16.h>

// One warp per 1024-element row; row slice staged in a PRIVATE per-thread
// shared-memory arena (each thread re-reads only addresses it wrote: no syncs,
// no conflicts). This removes the 32-reg row array -> 6 blocks/SM (75% occ)
// instead of 4 (50%), hiding DRAM + LDS latency. Per-element math identical
// to round 8 (native F2I/I2F/FRND conversion-pipe ops).

__global__ __launch_bounds__(256, 6) void qsoftmax_kernel(
    const float* __restrict__ x,
    const float* __restrict__ scale_p,
    const float* __restrict__ thr_p,
    float* __restrict__ out,
    int rows)
{
    __shared__ float4 sm4[2048];            // 8 rows x 256 float4 = 32KB
    const int lane = threadIdx.x & 31;
    const int wid  = threadIdx.x >> 5;
    const int row  = blockIdx.x * 8 + wid;
    if (row >= rows) return;

    const float4* __restrict__ xin = reinterpret_cast<const float4*>(x)  + (size_t)row * 256;
    float4* __restrict__ ov        = reinterpret_cast<float4*>(out)      + (size_t)row * 256;
    float4* __restrict__ b4        = sm4 + wid * 256;   // this warp's row buffer

    // ---- uniform constants (thread-invariant) ----
    const float sf     = *scale_p;
    const float thr    = *thr_p;
    const float inv_sf = 1.0f / sf;
    const float x0i    = floorf(-0.69314718f / sf);
    const float b_int  = floorf((float)(0.96963238 / 0.35815147) / sf);
    const float c_int  = floorf((float)(1.0 / 0.35815147) / (sf * sf));
    const float inv_x0 = 1.0f / x0i;
    const float lo     = 15.0f * x0i;
    const float t8     = floorf(thr * 256.0f);
    const float osA    = thr / 255.0f;
    const float osB    = (float)(1.0 / 255.0);                  // weak-promoted
    const float invA   = 1.0f / (4294967296.0f * osA);
    const float invB   = 1.0f / (float)(4294967296.0 / 255.0);  // weak-promoted

    // ---- pass 1: stream x -> smem, fold row max (raw x; mul by inv_sf>0 is monotone) ----
    float m = -3.4e38f;
    #pragma unroll
    for (int i = 0; i < 8; i++) {
        float4 t = xin[lane + 32 * i];
        b4[lane + 32 * i] = t;
        m = fmaxf(m, fmaxf(fmaxf(t.x, t.y), fmaxf(t.z, t.w)));
    }
    #pragma unroll
    for (int o = 16; o > 0; o >>= 1)
        m = fmaxf(m, __shfl_xor_sync(0xffffffffu, m, o));
    const float rmaxs = m * inv_sf;

    // ---- pass 2: LDS x -> integer exp -> STS e (in place); f32 running sums ----
    float s0 = 0.0f, s1 = 0.0f;
    #pragma unroll
    for (int i = 0; i < 8; i++) {
        float4 t = b4[lane + 32 * i];
        float* e = reinterpret_cast<float*>(&t);
        #pragma unroll
        for (int cidx = 0; cidx < 4; cidx++) {
            float xi = fmaxf(fmaf(e[cidx], inv_sf, -rmaxs), lo);  // ~[15*x0, +eps]
            float y  = xi * inv_x0;                    // [-eps,15]; trunc(-eps)=0 safe
            int   qi = (int)y;                         // F2I (trunc == floor here)
            float qf = (float)qi;                      // I2F
            float r  = fmaf(-x0i, qf, xi);
            float z  = fmaf(r, r + b_int, c_int);      // in [~556, 1116] > 0
            float p2 = __int_as_float(0x47000000 - (qi << 23));   // exact 2^(15-q)
            float ei = z * p2;                         // unfloored: frac<1 << quant step
            e[cidx] = ei;
            if (cidx & 1) s1 += ei; else s0 += ei;
        }
        b4[lane + 32 * i] = t;
    }
    float s = s0 + s1;
    #pragma unroll
    for (int o = 16; o > 0; o >>= 1)
        s += __shfl_xor_sync(0xffffffffu, s, o);

    // ---- per-row scalars (one true division) ----
    const float factor = floorf(4294967296.0f / s);
    const float approx = (t8 * s) * 0.00390625f;       // floor(thr*256)*sum/256

    // ---- pass 3: LDS e -> quantized output -> STG ----
    #pragma unroll
    for (int i = 0; i < 8; i++) {
        float4 t = b4[lane + 32 * i];
        float* e = reinterpret_cast<float*>(&t);
        #pragma unroll
        for (int cidx = 0; cidx < 4; cidx++) {
            float ei  = e[cidx];
            bool  isA = (ei <= approx);
            float inv = isA ? invA : invB;
            float os  = isA ? osA  : osB;
            float cap = isA ? 3.0e38f : 255.0f;
            float q   = fminf(floorf((ei * factor) * inv), cap);
            e[cidx] = q * os;
        }
        ov[lane + 32 * i] = t;
    }
}

extern "C" void kernel_launch(void* const* d_in, const int* in_sizes, int n_in,
                              void* d_out, int out_size) {
    const float* x     = (const float*)d_in[0];
    const float* scale = (const float*)d_in[1];
    const float* thr   = (const float*)d_in[2];
    float* out = (float*)d_out;
    const int rows = out_size / 1024;   // 32768
    qsoftmax_kernel<<<(rows + 7) / 8, 256>>>(x, scale, thr, out, rows);
}

// round 10
// speedup vs baseline: 1.5516x; 1.5516x over previous
#include <cuda_runtime.h>
#include <cuda_bf16.h>

// Round-8 structure (best: 36.6us kernel, 92% of HBM spec): one warp per
// 1024-element row, 32 elems/thread in registers, shuffle-only reductions,
// single launch, native conversion-pipe ops (F2I/I2F/FRND).
// Round-9 smem staging reverted (smem pipe serialization: 67.9us).
// New: launch_bounds(256,5) — live set is ~50 regs, so capping at 51 lifts
// occupancy 40->60% without true spills; fused per-row factor*inv constants
// save one FMUL/element.

__global__ __launch_bounds__(256, 5) void qsoftmax_kernel(
    const float* __restrict__ x,
    const float* __restrict__ scale_p,
    const float* __restrict__ thr_p,
    float* __restrict__ out,
    int rows)
{
    const int lane = threadIdx.x & 31;
    const int wid  = threadIdx.x >> 5;
    const int row  = blockIdx.x * 8 + wid;
    if (row >= rows) return;

    const float4* __restrict__ xin = reinterpret_cast<const float4*>(x)  + (size_t)row * 256;
    float4* __restrict__ ov        = reinterpret_cast<float4*>(out)      + (size_t)row * 256;

    // ---- load full row slice first (MLP=8) ----
    float4 v[8];
    #pragma unroll
    for (int i = 0; i < 8; i++) v[i] = xin[lane + 32 * i];

    // ---- uniform constants (thread-invariant) ----
    const float sf     = *scale_p;
    const float thr    = *thr_p;
    const float inv_sf = 1.0f / sf;
    const float x0i    = floorf(-0.69314718f / sf);
    const float b_int  = floorf((float)(0.96963238 / 0.35815147) / sf);
    const float c_int  = floorf((float)(1.0 / 0.35815147) / (sf * sf));
    const float inv_x0 = 1.0f / x0i;
    const float lo     = 15.0f * x0i;
    const float t8     = floorf(thr * 256.0f);
    const float osA    = thr / 255.0f;
    const float osB    = (float)(1.0 / 255.0);                  // weak-promoted
    const float invA   = 1.0f / (4294967296.0f * osA);
    const float invB   = 1.0f / (float)(4294967296.0 / 255.0);  // weak-promoted

    // ---- row max over raw x (RN mul by inv_sf>0 is monotonic) ----
    float m = fmaxf(fmaxf(v[0].x, v[0].y), fmaxf(v[0].z, v[0].w));
    #pragma unroll
    for (int i = 1; i < 8; i++)
        m = fmaxf(m, fmaxf(fmaxf(v[i].x, v[i].y), fmaxf(v[i].z, v[i].w)));
    #pragma unroll
    for (int o = 16; o > 0; o >>= 1)
        m = fmaxf(m, __shfl_xor_sync(0xffffffffu, m, o));
    const float rmaxs = m * inv_sf;

    // ---- integer exp, in place; f32 running sums ----
    float s0 = 0.0f, s1 = 0.0f;
    #pragma unroll
    for (int i = 0; i < 8; i++) {
        float* e = reinterpret_cast<float*>(&v[i]);
        #pragma unroll
        for (int cidx = 0; cidx < 4; cidx++) {
            float xi = fmaxf(fmaf(e[cidx], inv_sf, -rmaxs), lo);  // ~[15*x0, +eps]
            float y  = xi * inv_x0;                    // [-eps,15]; trunc(-eps)=0 safe
            int   qi = (int)y;                         // F2I (trunc == floor here)
            float qf = (float)qi;                      // I2F
            float r  = fmaf(-x0i, qf, xi);
            float z  = fmaf(r, r + b_int, c_int);      // in [~556, 1116] > 0
            float p2 = __int_as_float(0x47000000 - (qi << 23));   // exact 2^(15-q)
            float ei = z * p2;                         // unfloored: frac<1 << quant step
            e[cidx] = ei;
            if (cidx & 1) s1 += ei; else s0 += ei;
        }
    }
    float s = s0 + s1;
    #pragma unroll
    for (int o = 16; o > 0; o >>= 1)
        s += __shfl_xor_sync(0xffffffffu, s, o);

    // ---- per-row scalars (one true division; fused factor*inv constants) ----
    const float factor = floorf(4294967296.0f / s);
    const float approx = (t8 * s) * 0.00390625f;       // floor(thr*256)*sum/256
    const float cfA    = factor * invA;
    const float cfB    = factor * invB;

    // ---- quantized output: predicated selects, native FRND floor ----
    #pragma unroll
    for (int i = 0; i < 8; i++) {
        float* e = reinterpret_cast<float*>(&v[i]);
        #pragma unroll
        for (int cidx = 0; cidx < 4; cidx++) {
            float ei  = e[cidx];
            bool  isA = (ei <= approx);
            float cf  = isA ? cfA : cfB;
            float os  = isA ? osA : osB;
            float cap = isA ? 3.0e38f : 255.0f;
            float q   = fminf(floorf(ei * cf), cap);
            e[cidx] = q * os;
        }
        ov[lane + 32 * i] = v[i];
    }
}

extern "C" void kernel_launch(void* const* d_in, const int* in_sizes, int n_in,
                              void* d_out, int out_size) {
    const float* x     = (const float*)d_in[0];
    const float* scale = (const float*)d_in[1];
    const float* thr   = (const float*)d_in[2];
    float* out = (float*)d_out;
    const int rows = out_size / 1024;   // 32768
    qsoftmax_kernel<<<(rows + 7) / 8, 256>>>(x, scale, thr, out, rows);
}